// round 14
// baseline (speedup 1.0000x reference)
#include <cuda_runtime.h>

typedef unsigned long long u64;

#define BT  256   // threads per block
#define XPT 2     // vectors per thread
#define NP  128   // codeword pairs
#define CH  4     // pairs per chunk (8 codewords)
#define NC  (NP/CH)   // 32 chunks
#define PSTRIDE 6     // u64 per pair record (48B: walks all 8 16B bank slots)

__device__ __forceinline__ u64 pk2(float lo, float hi) {
    u64 r;
    asm("mov.b64 %0, {%1, %2};" : "=l"(r) : "f"(lo), "f"(hi));
    return r;
}
__device__ __forceinline__ void upk2(u64 v, float& lo, float& hi) {
    asm("mov.b64 {%0, %1}, %2;" : "=f"(lo), "=f"(hi) : "l"(v));
}
// Blackwell packed fp32 FMA: per-lane IEEE fma
__device__ __forceinline__ u64 ffma2(u64 a, u64 b, u64 c) {
    u64 d;
    asm("fma.rn.f32x2 %0, %1, %2, %3;" : "=l"(d) : "l"(a), "l"(b), "l"(c));
    return d;
}
// ||c||^2 with a FIXED IEEE op order — the only way q is ever computed.
__device__ __forceinline__ float qnorm(float4 a) {
    return __fmaf_rn(a.w, a.w, __fmaf_rn(a.z, a.z, __fmaf_rn(a.y, a.y, __fmul_rn(a.x, a.x))));
}

__global__ void __launch_bounds__(BT, 5)
vq_kernel(const float4* __restrict__ X,
          const float4* __restrict__ C,
          float4* __restrict__ outX,
          float* __restrict__ outS,
          int B)
{
    // Interleaved packed codebook: pair p = {ab0, ab1, cd0, cd1, q, pad}
    // at u64 index p*6 (16B-aligned; 48B stride spreads banks for the
    // chunk-divergent recovery loads).
    __shared__ u64 sP[NP * PSTRIDE];

    const int t = threadIdx.x;

    if (t < NP) {
        float4 a = C[2 * t];
        float4 b = C[2 * t + 1];
        sP[t * PSTRIDE + 0] = pk2(a.x, b.x);
        sP[t * PSTRIDE + 1] = pk2(a.y, b.y);
        sP[t * PSTRIDE + 2] = pk2(a.z, b.z);
        sP[t * PSTRIDE + 3] = pk2(a.w, b.w);
        sP[t * PSTRIDE + 4] = pk2(qnorm(a), qnorm(b));
    }
    __syncthreads();

    const int base = blockIdx.x * (BT * XPT) + t;

    u64 y0[XPT], y1[XPT], y2[XPT], y3[XPT];
    float bv[XPT];
    int   cid[XPT];

#pragma unroll
    for (int j = 0; j < XPT; j++) {
        int idx = base + j * BT;
        float4 x = (idx < B) ? X[idx] : make_float4(0.f, 0.f, 0.f, 0.f);
        float m0 = -2.0f * x.x, m1 = -2.0f * x.y, m2 = -2.0f * x.z, m3 = -2.0f * x.w;
        y0[j] = pk2(m0, m0);
        y1[j] = pk2(m1, m1);
        y2[j] = pk2(m2, m2);
        y3[j] = pk2(m3, m3);
        bv[j] = 3.402823466e38f;
        cid[j] = 0;
    }

    // Main loop: val_k = ||c_k||^2 - 2 x.c_k (same argmin as full distance).
    // Per pair·vec: 4 FFMA2 + 2 FMNMX. Scalar setp/sel/min once per 4-pair chunk.
#pragma unroll 2
    for (int c = 0; c < NC; c++) {
        float cm[XPT];
#pragma unroll
        for (int i = 0; i < CH; i++) {
            const int p = c * CH + i;
            const ulonglong2 ab = *(const ulonglong2*)&sP[p * PSTRIDE + 0]; // bcast
            const ulonglong2 cd = *(const ulonglong2*)&sP[p * PSTRIDE + 2];
            const u64        q  = sP[p * PSTRIDE + 4];
#pragma unroll
            for (int j = 0; j < XPT; j++) {
                u64 acc = ffma2(y0[j], ab.x, q);
                acc = ffma2(y1[j], ab.y, acc);
                acc = ffma2(y2[j], cd.x, acc);
                acc = ffma2(y3[j], cd.y, acc);
                float lo, hi;
                upk2(acc, lo, hi);
                float pv = fminf(lo, hi);
                cm[j] = (i == 0) ? pv : fminf(cm[j], pv);
            }
        }
#pragma unroll
        for (int j = 0; j < XPT; j++) {
            if (cm[j] < bv[j]) cid[j] = c;   // strict <: earlier chunk wins ties
            bv[j] = fminf(bv[j], cm[j]);     // FMNMX, lat 4
        }
    }

    // Recovery: replay the winning chunk's 4 pairs from smem (12 divergent LDS
    // per vector; 192B chunk stride over the 48B-interleaved layout keeps bank
    // conflicts <=4-way). FMNMX returns inputs bitwise, so d == bv is guaranteed
    // for the winner; FFMA2 chain identical to the main loop. Descending scan
    // with overwrite => smallest index wins (jnp.argmin first-occurrence).
#pragma unroll
    for (int j = 0; j < XPT; j++) {
        const int pb = cid[j] * CH;
        int bi = 0;
        float wx = 0.f, wy = 0.f, wz = 0.f, ww = 0.f;
#pragma unroll
        for (int i = CH - 1; i >= 0; i--) {
            const int p = pb + i;
            const ulonglong2 ab = *(const ulonglong2*)&sP[p * PSTRIDE + 0];
            const ulonglong2 cd = *(const ulonglong2*)&sP[p * PSTRIDE + 2];
            const u64        q  = sP[p * PSTRIDE + 4];
            u64 acc = ffma2(y0[j], ab.x, q);
            acc = ffma2(y1[j], ab.y, acc);
            acc = ffma2(y2[j], cd.x, acc);
            acc = ffma2(y3[j], cd.y, acc);
            float lo, hi;
            upk2(acc, lo, hi);
            float a0, b0, a1, b1, a2, b2, a3, b3;
            upk2(ab.x, a0, b0); upk2(ab.y, a1, b1);
            upk2(cd.x, a2, b2); upk2(cd.y, a3, b3);
            if (hi == bv[j]) { bi = 2 * p + 1; wx = b0; wy = b1; wz = b2; ww = b3; }
            if (lo == bv[j]) { bi = 2 * p;     wx = a0; wy = a1; wz = a2; ww = a3; }
        }
        const int idx = base + j * BT;
        if (idx < B) {
            outX[idx] = make_float4(wx, wy, wz, ww);
            outS[idx] = (float)bi;           // harness reads d_out as float32
        }
    }
}

extern "C" void kernel_launch(void* const* d_in, const int* in_sizes, int n_in,
                              void* d_out, int out_size)
{
    const float4* X = (const float4*)d_in[0];   // [B, 4] fp32
    const float4* C = (const float4*)d_in[1];   // [256, 4] fp32 codebook

    const int B = in_sizes[0] / 4;

    float4* outX = (float4*)d_out;                  // hatX [B,4] fp32
    float*  outS = (float*)d_out + 4 * (size_t)B;   // state [B] as fp32

    const int grid = (B + BT * XPT - 1) / (BT * XPT);
    vq_kernel<<<grid, BT>>>(X, C, outX, outS, B);
}

// round 15
// speedup vs baseline: 1.2400x; 1.2400x over previous
#include <cuda_runtime.h>

typedef unsigned long long u64;

#define BT   256   // threads per block
#define XPT  2     // vectors per thread
#define NP   128   // codeword pairs
#define TILE (BT * XPT)

__device__ __forceinline__ u64 pk2(float lo, float hi) {
    u64 r;
    asm("mov.b64 %0, {%1, %2};" : "=l"(r) : "f"(lo), "f"(hi));
    return r;
}
__device__ __forceinline__ void upk2(u64 v, float& lo, float& hi) {
    asm("mov.b64 {%0, %1}, %2;" : "=f"(lo), "=f"(hi) : "l"(v));
}
// Blackwell packed fp32 FMA (rt_SMSP~4: throughput == 2 scalar FFMA, but 1 issue slot)
__device__ __forceinline__ u64 ffma2(u64 a, u64 b, u64 c) {
    u64 d;
    asm("fma.rn.f32x2 %0, %1, %2, %3;" : "=l"(d) : "l"(a), "l"(b), "l"(c));
    return d;
}
// ||c||^2 with a FIXED IEEE op order — the only way q is ever computed.
__device__ __forceinline__ float qnorm(float4 a) {
    return __fmaf_rn(a.w, a.w, __fmaf_rn(a.z, a.z, __fmaf_rn(a.y, a.y, __fmul_rn(a.x, a.x))));
}

template <bool GUARD>
__global__ void __launch_bounds__(BT, 6)
vq_kernel(const float4* __restrict__ X,
          const float4* __restrict__ C,
          float4* __restrict__ outX,
          float* __restrict__ outS,
          int B)
{
    // Packed codebook: pair p covers codewords (2p, 2p+1)
    __shared__ ulonglong2 sAB[NP];      // (dim0 pair, dim1 pair)
    __shared__ ulonglong2 sCD[NP];      // (dim2 pair, dim3 pair)
    __shared__ ulonglong2 sQ2[NP / 2];  // ||c||^2 for pairs (2i,2i+1) in one 16B slot

    const int t = threadIdx.x;

    if (t < NP) {
        float4 a = C[2 * t];
        float4 b = C[2 * t + 1];
        sAB[t] = make_ulonglong2(pk2(a.x, b.x), pk2(a.y, b.y));
        sCD[t] = make_ulonglong2(pk2(a.z, b.z), pk2(a.w, b.w));
        u64 qp = pk2(qnorm(a), qnorm(b));
        if (t & 1) sQ2[t >> 1].y = qp; else sQ2[t >> 1].x = qp;
    }
    __syncthreads();

    const int base = blockIdx.x * TILE + t;

    u64 y0[XPT], y1[XPT], y2[XPT], y3[XPT];
    float bv[XPT];
    int   pid[XPT];

#pragma unroll
    for (int j = 0; j < XPT; j++) {
        int idx = base + j * BT;
        float4 x;
        if (GUARD) x = (idx < B) ? X[idx] : make_float4(0.f, 0.f, 0.f, 0.f);
        else       x = X[idx];
        float m0 = -2.0f * x.x, m1 = -2.0f * x.y, m2 = -2.0f * x.z, m3 = -2.0f * x.w;
        y0[j] = pk2(m0, m0);
        y1[j] = pk2(m1, m1);
        y2[j] = pk2(m2, m2);
        y3[j] = pk2(m3, m3);
        bv[j] = 3.402823466e38f;
        pid[j] = 0;
    }

    // Main loop: val_k = ||c_k||^2 - 2 x.c_k (same argmin as full distance).
    // fma pipe binds (FFMA2 rt~4); alu + LDS hide under its shadow.
#pragma unroll 8
    for (int p2 = 0; p2 < NP / 2; p2++) {
        const ulonglong2 qq = sQ2[p2];   // broadcast LDS, conflict-free
        {
            const int p = 2 * p2;
            const ulonglong2 ab = sAB[p];
            const ulonglong2 cd = sCD[p];
#pragma unroll
            for (int j = 0; j < XPT; j++) {
                u64 acc = ffma2(y0[j], ab.x, qq.x);
                acc = ffma2(y1[j], ab.y, acc);
                acc = ffma2(y2[j], cd.x, acc);
                acc = ffma2(y3[j], cd.y, acc);
                float lo, hi;
                upk2(acc, lo, hi);
                float pv = fminf(lo, hi);
                if (pv < bv[j]) pid[j] = p;   // strict <: earlier pair wins ties
                bv[j] = fminf(bv[j], pv);     // FMNMX, lat 4
            }
        }
        {
            const int p = 2 * p2 + 1;
            const ulonglong2 ab = sAB[p];
            const ulonglong2 cd = sCD[p];
#pragma unroll
            for (int j = 0; j < XPT; j++) {
                u64 acc = ffma2(y0[j], ab.x, qq.y);
                acc = ffma2(y1[j], ab.y, acc);
                acc = ffma2(y2[j], cd.x, acc);
                acc = ffma2(y3[j], cd.y, acc);
                float lo, hi;
                upk2(acc, lo, hi);
                float pv = fminf(lo, hi);
                if (pv < bv[j]) pid[j] = p;
                bv[j] = fminf(bv[j], pv);
            }
        }
    }

    // Recovery: replay the winning pair's bitwise-identical FFMA2 chain (3 divergent
    // LDS per vector, once). FMNMX returns an input exactly, so hi<lo resolves the
    // within-pair index; ties prefer lo (= smaller index), matching jnp.argmin
    // first-occurrence. Winner components come from the pair registers (no gather).
#pragma unroll
    for (int j = 0; j < XPT; j++) {
        const int p = pid[j];
        const ulonglong2 rab = sAB[p];
        const ulonglong2 rcd = sCD[p];
        const ulonglong2 rqq = sQ2[p >> 1];
        const u64 rq = (p & 1) ? rqq.y : rqq.x;
        u64 acc = ffma2(y0[j], rab.x, rq);
        acc = ffma2(y1[j], rab.y, acc);
        acc = ffma2(y2[j], rcd.x, acc);
        acc = ffma2(y3[j], rcd.y, acc);
        float lo, hi;
        upk2(acc, lo, hi);
        const bool h = (hi < lo);
        float a0, b0, a1, b1, a2, b2, a3, b3;
        upk2(rab.x, a0, b0); upk2(rab.y, a1, b1);
        upk2(rcd.x, a2, b2); upk2(rcd.y, a3, b3);
        const int idx = base + j * BT;
        if (!GUARD || idx < B) {
            outX[idx] = make_float4(h ? b0 : a0, h ? b1 : a1,
                                    h ? b2 : a2, h ? b3 : a3);
            outS[idx] = (float)(2 * p + (h ? 1 : 0));   // harness reads d_out as f32
        }
    }
}

extern "C" void kernel_launch(void* const* d_in, const int* in_sizes, int n_in,
                              void* d_out, int out_size)
{
    const float4* X = (const float4*)d_in[0];   // [B, 4] fp32
    const float4* C = (const float4*)d_in[1];   // [256, 4] fp32 codebook

    const int B = in_sizes[0] / 4;

    float4* outX = (float4*)d_out;                  // hatX [B,4] fp32
    float*  outS = (float*)d_out + 4 * (size_t)B;   // state [B] as fp32

    if (B % TILE == 0) {
        vq_kernel<false><<<B / TILE, BT>>>(X, C, outX, outS, B);
    } else {
        vq_kernel<true><<<(B + TILE - 1) / TILE, BT>>>(X, C, outX, outS, B);
    }
}